// round 9
// baseline (speedup 1.0000x reference)
#include <cuda_runtime.h>
#include <cuda_fp16.h>
#include <cstdint>

#define BB 4
#define HH 8
#define NN 2048
#define BHN (BB*HH)
#define MROWS (BB*NN)

// ---------------- scratch (static device, no allocs) ----------------
__device__ __half g_q16[BHN * NN * 32];   // [bh][n][qhi16|qlo16], 0.25*log2e folded
__device__ __half g_k16[BHN * NN * 32];   // [bh][n][khi16|klo16]
__device__ __half g_vh16[BHN * 16 * NN];  // [bh][e][n]  V^T (fp16-rn)
__device__ float  g_ctx[MROWS * 128];     // [b*N+n][h*16+e]

// ---------------- helpers ----------------
__device__ __forceinline__ float ex2f_fast(float x) {
    float y; asm("ex2.approx.ftz.f32 %0, %1;" : "=f"(y) : "f"(x)); return y;
}
__device__ __forceinline__ float dot4acc(float4 a, float4 b, float t) {
    t = fmaf(a.x, b.x, t); t = fmaf(a.y, b.y, t);
    t = fmaf(a.z, b.z, t); t = fmaf(a.w, b.w, t);
    return t;
}
__device__ __forceinline__ float qmax(float v) {
    v = fmaxf(v, __shfl_xor_sync(0xFFFFFFFFu, v, 1));
    v = fmaxf(v, __shfl_xor_sync(0xFFFFFFFFu, v, 2));
    return v;
}
__device__ __forceinline__ float qsum(float v) {
    v += __shfl_xor_sync(0xFFFFFFFFu, v, 1);
    v += __shfl_xor_sync(0xFFFFFFFFu, v, 2);
    return v;
}
__device__ __forceinline__ void mma_f16(float* d, const uint32_t* a,
                                        uint32_t b0, uint32_t b1) {
    asm volatile(
        "mma.sync.aligned.m16n8k16.row.col.f32.f16.f16.f32 "
        "{%0,%1,%2,%3}, {%4,%5,%6,%7}, {%8,%9}, {%0,%1,%2,%3};"
        : "+f"(d[0]), "+f"(d[1]), "+f"(d[2]), "+f"(d[3])
        : "r"(a[0]), "r"(a[1]), "r"(a[2]), "r"(a[3]), "r"(b0), "r"(b1));
}
__device__ __forceinline__ uint32_t cvt_h2(float lo, float hi) {
    uint32_t r;
    asm("cvt.rn.f16x2.f32 %0, %1, %2;" : "=r"(r) : "f"(hi), "f"(lo));
    return r;
}
__device__ __forceinline__ uint32_t smem_u32(const void* p) {
    uint32_t a;
    asm("{ .reg .u64 t; cvta.to.shared.u64 t, %1; cvt.u32.u64 %0, t; }" : "=r"(a) : "l"(p));
    return a;
}
__device__ __forceinline__ void cp_async16(uint32_t dst, const void* src) {
    asm volatile("cp.async.ca.shared.global [%0], [%1], 16;" :: "r"(dst), "l"(src));
}
#define CP_COMMIT()  asm volatile("cp.async.commit_group;" ::: "memory")
#define CP_WAIT(N)   asm volatile("cp.async.wait_group " #N ";" ::: "memory")

// ---------------- Q/K projection + fp16 hi/lo split ----------------
__global__ void __launch_bounds__(128) projqk_kernel(
    const float* __restrict__ Aq, const float* __restrict__ Ak,
    const float* __restrict__ Wq, const float* __restrict__ Wk,
    const float* __restrict__ bq, const float* __restrict__ bk, float alpha_q)
{
    const int TM = 32;
    __shared__ float As[TM][128];
    __shared__ float Ws[32][129];
    const bool is_k = (blockIdx.y != 0);
    const float* A    = is_k ? Ak : Aq;
    const float* W    = is_k ? Wk : Wq;
    const float* bias = is_k ? bk : bq;
    __half*      outp = is_k ? g_k16 : g_q16;
    const float alpha = is_k ? 1.0f : alpha_q;
    const int r0 = blockIdx.x * TM;
    const int c  = threadIdx.x;
    {
        const float4* Ag = (const float4*)(A + (size_t)r0 * 128);
        float4* Asv = (float4*)&As[0][0];
        #pragma unroll
        for (int i = 0; i < 8; i++) Asv[c + 128 * i] = Ag[c + 128 * i];
    }
    float acc[TM];
    #pragma unroll
    for (int r = 0; r < TM; r++) acc[r] = 0.f;
    for (int k0 = 0; k0 < 128; k0 += 32) {
        __syncthreads();
        const float4* wg = (const float4*)(W + c * 128 + k0);
        #pragma unroll
        for (int i = 0; i < 8; i++) {
            float4 w4 = wg[i];
            Ws[i*4+0][c] = w4.x; Ws[i*4+1][c] = w4.y;
            Ws[i*4+2][c] = w4.z; Ws[i*4+3][c] = w4.w;
        }
        __syncthreads();
        #pragma unroll
        for (int kk = 0; kk < 32; kk += 4) {
            const float w0 = Ws[kk+0][c], w1 = Ws[kk+1][c];
            const float w2 = Ws[kk+2][c], w3 = Ws[kk+3][c];
            #pragma unroll
            for (int r = 0; r < TM; r++) {
                float4 a4 = *(const float4*)&As[r][k0 + kk];
                float t = acc[r];
                t = fmaf(a4.x, w0, t); t = fmaf(a4.y, w1, t);
                t = fmaf(a4.z, w2, t); t = fmaf(a4.w, w3, t);
                acc[r] = t;
            }
        }
    }
    const float bc = bias[c];
    const int h = c >> 4, d = c & 15;
    #pragma unroll
    for (int r = 0; r < TM; r++) {
        const int row = r0 + r;
        const int b = row >> 11, n = row & 2047;
        const float x = (acc[r] + bc) * alpha;
        const __half hi = __float2half_rn(x);
        const size_t base = ((size_t)((b * HH + h) * NN + n)) * 32;
        outp[base + d]      = hi;
        outp[base + 16 + d] = __float2half_rn(x - __half2float(hi));
    }
}

// ---------------- V projection + transpose (fp16-rn) ----------------
__global__ void __launch_bounds__(128) projvt_kernel(
    const float* __restrict__ value, const float* __restrict__ Wv,
    const float* __restrict__ bv)
{
    __shared__ float Wsm[16][17];
    __shared__ float bsm[16];
    __shared__ __half thi[16][128];
    const int bh = blockIdx.x >> 4, nt = blockIdx.x & 15;
    const int b = bh >> 3, h = bh & 7;
    const int t = threadIdx.x;
    if (t < 16) bsm[t] = bv[h * 16 + t];
    for (int i = t; i < 256; i += 128)
        Wsm[i >> 4][i & 15] = Wv[(h * 16 + (i >> 4)) * 16 + (i & 15)];
    __syncthreads();
    const int n = nt * 128 + t;
    const float4* a = (const float4*)(value + ((size_t)(b * NN + n) << 4));
    const float4 a0 = a[0], a1 = a[1], a2 = a[2], a3 = a[3];
    const float av[16] = {a0.x,a0.y,a0.z,a0.w, a1.x,a1.y,a1.z,a1.w,
                          a2.x,a2.y,a2.z,a2.w, a3.x,a3.y,a3.z,a3.w};
    #pragma unroll
    for (int e = 0; e < 16; e++) {
        float acc = bsm[e];
        #pragma unroll
        for (int k = 0; k < 16; k++) acc = fmaf(av[k], Wsm[e][k], acc);
        thi[e][t] = __float2half_rn(acc);
    }
    __syncthreads();
    for (int i = t; i < 2048; i += 128) {
        const int e = i >> 7, j = i & 127;
        g_vh16[((size_t)bh * 16 + e) * NN + nt * 128 + j] = thi[e][j];
    }
}

// ---------------- fp16 mma.sync flash attention (8 warps, cp.async x2 buf) ----------------
// 512 CTAs = 32 bh x 16 q-tiles of 128 rows; 256 threads; warp owns 16 q-rows.
// QK: 3 compensated MMAs; PV: 1 MMA (V fp16-rn).
__global__ void __launch_bounds__(256) attn_mma_kernel()
{
    __shared__ __align__(16) __half Ksm[2][128 * 40];   // [buf][key][hi16|lo16|pad8]
    __shared__ __align__(16) __half Vh[2][16 * 136];    // [buf][e][key]

    const int tid = threadIdx.x, lane = tid & 31, wid = tid >> 5;
    const int bh = blockIdx.x >> 4, qt = blockIdx.x & 15;
    const int qrow0 = qt * 128 + wid * 16;
    const int lq = lane >> 2;   // 0..7
    const int lc = lane & 3;    // 0..3

    // Q fragments hi/lo (one-time gmem load; warp = one m16 block)
    uint32_t qh[4], ql[4];
    {
        const __half* p0 = g_q16 + ((size_t)(bh * NN + qrow0 + lq)) * 32 + lc * 2;
        qh[0] = *(const uint32_t*)(p0);
        qh[1] = *(const uint32_t*)(p0 + 256);
        qh[2] = *(const uint32_t*)(p0 + 8);
        qh[3] = *(const uint32_t*)(p0 + 264);
        ql[0] = *(const uint32_t*)(p0 + 16);
        ql[1] = *(const uint32_t*)(p0 + 272);
        ql[2] = *(const uint32_t*)(p0 + 24);
        ql[3] = *(const uint32_t*)(p0 + 280);
    }

    float mr[2] = {-1e30f, -1e30f}, lrow[2] = {0.f, 0.f};
    float o[2][4];
    #pragma unroll
    for (int nb = 0; nb < 2; nb++)
        #pragma unroll
        for (int i = 0; i < 4; i++) o[nb][i] = 0.f;

    const char* kg  = (const char*)(g_k16 + ((size_t)bh * NN) * 32);
    const char* vhg = (const char*)(g_vh16 + (size_t)bh * 16 * NN);

    // per-thread staging addresses (smem side precomputed)
    const uint32_t ks_base = smem_u32(&Ksm[0][0]);
    const uint32_t vs_base = smem_u32(&Vh[0][0]);
    const int kj0 = tid;                    // chunks tid, tid+256
    const int key0 = kj0 >> 2, seg0 = kj0 & 3;
    const int kj1 = tid + 256;
    const int key1 = kj1 >> 2, seg1 = kj1 & 3;
    const int ve = tid >> 4, vseg = tid & 15;
    const uint32_t kdst0 = (uint32_t)(key0 * 80 + seg0 * 16);
    const uint32_t kdst1 = (uint32_t)(key1 * 80 + seg1 * 16);
    const uint32_t vdst  = (uint32_t)(ve * 272 + vseg * 16);
    const size_t ksrc0 = (size_t)(key0 * 64 + seg0 * 16);
    const size_t ksrc1 = (size_t)(key1 * 64 + seg1 * 16);

    #define STAGE(T0, BUF) do { \
        const uint32_t kb_ = ks_base + (BUF) * (128 * 80); \
        const uint32_t vb_ = vs_base + (BUF) * (16 * 272); \
        const size_t koff_ = (size_t)(T0) * 64; \
        cp_async16(kb_ + kdst0, kg + koff_ + ksrc0); \
        cp_async16(kb_ + kdst1, kg + koff_ + ksrc1); \
        cp_async16(vb_ + vdst, vhg + ((size_t)ve * NN + (T0) + vseg * 8) * 2); \
        CP_COMMIT(); \
    } while (0)

    STAGE(0, 0);

    for (int t = 0; t < 16; t++) {
        const int cur = t & 1;
        if (t < 15) { STAGE((t + 1) * 128, 1 - cur); CP_WAIT(1); }
        else        { CP_WAIT(0); }
        __syncthreads();

        const __half* Kb = Ksm[cur];
        const __half* Vb = Vh[cur];

        // ---- QK ----
        float S[16][4];
        #pragma unroll
        for (int n = 0; n < 16; n++)
            #pragma unroll
            for (int i = 0; i < 4; i++) S[n][i] = 0.f;

        #pragma unroll
        for (int n = 0; n < 16; n++) {
            const __half* kb = Kb + (n * 8 + lq) * 40 + lc * 2;
            const uint32_t bh0 = *(const uint32_t*)kb;
            const uint32_t bh1 = *(const uint32_t*)(kb + 8);
            const uint32_t bl0 = *(const uint32_t*)(kb + 16);
            const uint32_t bl1 = *(const uint32_t*)(kb + 24);
            mma_f16(S[n], qh, bh0, bh1);
            mma_f16(S[n], ql, bh0, bh1);
            mma_f16(S[n], qh, bl0, bl1);
        }

        // ---- softmax (rows lq, lq+8) ----
        float cm0 = -1e30f, cm1 = -1e30f;
        #pragma unroll
        for (int n = 0; n < 16; n++) {
            cm0 = fmaxf(cm0, fmaxf(S[n][0], S[n][1]));
            cm1 = fmaxf(cm1, fmaxf(S[n][2], S[n][3]));
        }
        {
            const float mn0 = fmaxf(mr[0], qmax(cm0));
            const float c0 = ex2f_fast(mr[0] - mn0);
            mr[0] = mn0; lrow[0] *= c0;
            const float mn1 = fmaxf(mr[1], qmax(cm1));
            const float c1 = ex2f_fast(mr[1] - mn1);
            mr[1] = mn1; lrow[1] *= c1;
            #pragma unroll
            for (int nb = 0; nb < 2; nb++) {
                o[nb][0] *= c0; o[nb][1] *= c0;
                o[nb][2] *= c1; o[nb][3] *= c1;
            }
        }
        float rs0 = 0.f, rs1 = 0.f;
        #pragma unroll
        for (int n = 0; n < 16; n++) {
            const float p0 = ex2f_fast(S[n][0] - mr[0]);
            const float p1 = ex2f_fast(S[n][1] - mr[0]);
            const float p2 = ex2f_fast(S[n][2] - mr[1]);
            const float p3 = ex2f_fast(S[n][3] - mr[1]);
            rs0 += p0 + p1;
            rs1 += p2 + p3;
            S[n][0] = __uint_as_float(cvt_h2(p0, p1));  // keys (2lc,2lc+1), row lq
            S[n][1] = __uint_as_float(cvt_h2(p2, p3));  // keys (2lc,2lc+1), row lq+8
        }
        lrow[0] += qsum(rs0);
        lrow[1] += qsum(rs1);

        // ---- PV: o += P*V ----
        #pragma unroll
        for (int kb = 0; kb < 8; kb++) {
            const uint32_t ah[4] = {
                __float_as_uint(S[2*kb][0]),   __float_as_uint(S[2*kb][1]),
                __float_as_uint(S[2*kb+1][0]), __float_as_uint(S[2*kb+1][1])
            };
            #pragma unroll
            for (int nb = 0; nb < 2; nb++) {
                const __half* vb = Vb + (nb * 8 + lq) * 136 + kb * 16 + lc * 2;
                const uint32_t b0 = *(const uint32_t*)vb;
                const uint32_t b1 = *(const uint32_t*)(vb + 8);
                mma_f16(o[nb], ah, b0, b1);
            }
        }
        __syncthreads();
    }

    // ---- epilogue ----
    const float inv0 = 1.0f / lrow[0];
    const float inv1 = 1.0f / lrow[1];
    const int b = bh >> 3, hh = bh & 7;
    const int rA = qrow0 + lq;
    #pragma unroll
    for (int nb = 0; nb < 2; nb++) {
        const int e0 = nb * 8 + lc * 2;
        float* pA = g_ctx + ((size_t)(b * NN + rA)) * 128 + hh * 16 + e0;
        float* pB = pA + 8 * 128;
        *(float2*)pA = make_float2(o[nb][0] * inv0, o[nb][1] * inv0);
        *(float2*)pB = make_float2(o[nb][2] * inv1, o[nb][3] * inv1);
    }
    #undef STAGE
}

// ---------------- output projection (32 rows/CTA, 2 outputs/thread) ----------------
__global__ void __launch_bounds__(256) outproj_kernel(
    const float* __restrict__ Wo, const float* __restrict__ bo,
    float* __restrict__ out)
{
    __shared__ float Cs[32][128];
    __shared__ float Ws[16][132];
    const int r0 = blockIdx.x * 32;
    const float4* cg = (const float4*)(g_ctx + ((size_t)r0 << 7));
    float4* csv = (float4*)&Cs[0][0];
    #pragma unroll
    for (int i = 0; i < 4; i++)
        csv[threadIdx.x + 256 * i] = cg[threadIdx.x + 256 * i];
    for (int i = threadIdx.x; i < 2048; i += 256) Ws[i >> 7][i & 127] = Wo[i];
    __syncthreads();
    const int r = threadIdx.x >> 4, c = threadIdx.x & 15;
    float acc0 = bo[c], acc1 = bo[c];
    #pragma unroll
    for (int kk = 0; kk < 128; kk += 4) {
        float4 w = *(const float4*)&Ws[c][kk];
        float4 a0 = *(const float4*)&Cs[r][kk];
        float4 a1 = *(const float4*)&Cs[r + 16][kk];
        acc0 = dot4acc(a0, w, acc0);
        acc1 = dot4acc(a1, w, acc1);
    }
    out[((size_t)(r0 + r) << 4) + c]      = acc0;
    out[((size_t)(r0 + r + 16) << 4) + c] = acc1;
}

// ---------------- launcher ----------------
extern "C" void kernel_launch(void* const* d_in, const int* in_sizes, int n_in,
                              void* d_out, int out_size)
{
    const float* query = (const float*)d_in[0];
    const float* key   = (const float*)d_in[1];
    const float* value = (const float*)d_in[2];
    const float* Wq    = (const float*)d_in[3];
    const float* bq    = (const float*)d_in[4];
    const float* Wk    = (const float*)d_in[5];
    const float* bk    = (const float*)d_in[6];
    const float* Wv    = (const float*)d_in[7];
    const float* bv    = (const float*)d_in[8];
    const float* Wo    = (const float*)d_in[9];
    const float* bo    = (const float*)d_in[10];
    float* out = (float*)d_out;

    const float alpha_q = 0.25f * 1.4426950408889634f;

    dim3 gqk(MROWS / 32, 2);
    projqk_kernel<<<gqk, 128>>>(query, key, Wq, Wk, bq, bk, alpha_q);
    projvt_kernel<<<BHN * 16, 128>>>(value, Wv, bv);
    attn_mma_kernel<<<BHN * 16, 256>>>();
    outproj_kernel<<<MROWS / 32, 256>>>(Wo, bo, out);
}

// round 10
// speedup vs baseline: 1.0780x; 1.0780x over previous
#include <cuda_runtime.h>
#include <cuda_fp16.h>
#include <cstdint>

#define BB 4
#define HH 8
#define NN 2048
#define BHN (BB*HH)
#define MROWS (BB*NN)

// ---------------- scratch (static device, no allocs) ----------------
__device__ __half g_q16[BHN * NN * 32];   // [bh][n][qhi16|qlo16], 0.25*log2e folded
__device__ __half g_k16[BHN * NN * 32];   // [bh][n][khi16|klo16]
__device__ __half g_vh16[BHN * 16 * NN];  // [bh][e][n]  V^T (fp16-rn)
__device__ __half g_ctx16[MROWS * 128];   // [b*N+n][h*16+e]  fp16
__device__ __half g_Wh[2 * 128 * 128];    // W hi: [q|k][c][k]
__device__ __half g_Wl[2 * 128 * 128];    // W lo residual

// ---------------- helpers ----------------
__device__ __forceinline__ float ex2f_fast(float x) {
    float y; asm("ex2.approx.ftz.f32 %0, %1;" : "=f"(y) : "f"(x)); return y;
}
__device__ __forceinline__ float dot4acc(float4 a, float4 b, float t) {
    t = fmaf(a.x, b.x, t); t = fmaf(a.y, b.y, t);
    t = fmaf(a.z, b.z, t); t = fmaf(a.w, b.w, t);
    return t;
}
__device__ __forceinline__ float qmax(float v) {
    v = fmaxf(v, __shfl_xor_sync(0xFFFFFFFFu, v, 1));
    v = fmaxf(v, __shfl_xor_sync(0xFFFFFFFFu, v, 2));
    return v;
}
__device__ __forceinline__ float qsum(float v) {
    v += __shfl_xor_sync(0xFFFFFFFFu, v, 1);
    v += __shfl_xor_sync(0xFFFFFFFFu, v, 2);
    return v;
}
__device__ __forceinline__ void mma_f16(float* d, const uint32_t* a,
                                        uint32_t b0, uint32_t b1) {
    asm volatile(
        "mma.sync.aligned.m16n8k16.row.col.f32.f16.f16.f32 "
        "{%0,%1,%2,%3}, {%4,%5,%6,%7}, {%8,%9}, {%0,%1,%2,%3};"
        : "+f"(d[0]), "+f"(d[1]), "+f"(d[2]), "+f"(d[3])
        : "r"(a[0]), "r"(a[1]), "r"(a[2]), "r"(a[3]), "r"(b0), "r"(b1));
}
// packs: low half <- lo, high half <- hi
__device__ __forceinline__ uint32_t cvt_h2(float lo, float hi) {
    uint32_t r;
    asm("cvt.rn.f16x2.f32 %0, %1, %2;" : "=r"(r) : "f"(hi), "f"(lo));
    return r;
}
__device__ __forceinline__ float2 h2_to_f2(uint32_t u) {
    return __half22float2(*reinterpret_cast<__half2*>(&u));
}

// ---------------- W prep: split Wq/Wk into fp16 hi/lo ----------------
__global__ void __launch_bounds__(256) prepw_kernel(
    const float* __restrict__ Wq, const float* __restrict__ Wk)
{
    const int idx = blockIdx.x * 256 + threadIdx.x;    // 0..32767
    const int m = idx >> 14, rest = idx & 16383;
    const float x = (m ? Wk : Wq)[rest];
    const __half hi = __float2half_rn(x);
    g_Wh[idx] = hi;
    g_Wl[idx] = __float2half_rn(x - __half2float(hi));
}

// ---------------- Q/K projection on tensor cores ----------------
// out = (A[8192,128] @ W^T + bias) * alpha, 3-MMA hi/lo compensation,
// then fp16 hi/lo split into g_q16/g_k16 layout.
// grid (128, 2); 256 thr = 8 warps: warp = (rowgrp 0..3) x (colgrp 0..1).
__global__ void __launch_bounds__(256) projqk_mma_kernel(
    const float* __restrict__ Aq, const float* __restrict__ Ak,
    const float* __restrict__ bq, const float* __restrict__ bk, float alpha_q)
{
    const bool is_k = (blockIdx.y != 0);
    const float* A    = is_k ? Ak : Aq;
    const float* bias = is_k ? bk : bq;
    const __half* Wh  = g_Wh + (is_k ? 16384 : 0);
    const __half* Wl  = g_Wl + (is_k ? 16384 : 0);
    __half* outp      = is_k ? g_k16 : g_q16;
    const float alpha = is_k ? 1.0f : alpha_q;

    const int tid = threadIdx.x, lane = tid & 31, wid = tid >> 5;
    const int rg = wid >> 1, cg = wid & 1;
    const int lq = lane >> 2, lc = lane & 3;
    const int r0 = blockIdx.x * 64 + rg * 16;
    const int c0 = cg * 64;

    // A fragments hi/lo (fp32 global -> registers)
    uint32_t ah[8][4], al[8][4];
    {
        const float* Ar0 = A + (size_t)(r0 + lq) * 128;
        const float* Ar1 = Ar0 + 8 * 128;
        #pragma unroll
        for (int ks = 0; ks < 8; ks++) {
            const int k0 = ks * 16 + lc * 2;
            float2 f0 = *(const float2*)(Ar0 + k0);
            float2 f1 = *(const float2*)(Ar1 + k0);
            float2 f2 = *(const float2*)(Ar0 + k0 + 8);
            float2 f3 = *(const float2*)(Ar1 + k0 + 8);
            ah[ks][0] = cvt_h2(f0.x, f0.y);
            ah[ks][1] = cvt_h2(f1.x, f1.y);
            ah[ks][2] = cvt_h2(f2.x, f2.y);
            ah[ks][3] = cvt_h2(f3.x, f3.y);
            float2 h0 = h2_to_f2(ah[ks][0]), h1 = h2_to_f2(ah[ks][1]);
            float2 h2 = h2_to_f2(ah[ks][2]), h3 = h2_to_f2(ah[ks][3]);
            al[ks][0] = cvt_h2(f0.x - h0.x, f0.y - h0.y);
            al[ks][1] = cvt_h2(f1.x - h1.x, f1.y - h1.y);
            al[ks][2] = cvt_h2(f2.x - h2.x, f2.y - h2.y);
            al[ks][3] = cvt_h2(f3.x - h3.x, f3.y - h3.y);
        }
    }

    float D[8][4];
    #pragma unroll
    for (int nb = 0; nb < 8; nb++)
        #pragma unroll
        for (int i = 0; i < 4; i++) D[nb][i] = 0.f;

    #pragma unroll
    for (int nb = 0; nb < 8; nb++) {
        const int c = c0 + nb * 8 + lq;
        const __half* whp = Wh + (size_t)c * 128;
        const __half* wlp = Wl + (size_t)c * 128;
        #pragma unroll
        for (int ks = 0; ks < 8; ks++) {
            const int k0 = ks * 16 + lc * 2;
            const uint32_t bh0 = *(const uint32_t*)(whp + k0);
            const uint32_t bh1 = *(const uint32_t*)(whp + k0 + 8);
            const uint32_t bl0 = *(const uint32_t*)(wlp + k0);
            const uint32_t bl1 = *(const uint32_t*)(wlp + k0 + 8);
            mma_f16(D[nb], ah[ks], bh0, bh1);
            mma_f16(D[nb], al[ks], bh0, bh1);
            mma_f16(D[nb], ah[ks], bl0, bl1);
        }
    }

    // epilogue: add bias, scale, fp16 hi/lo split, scatter to [bh][n][32]
    #pragma unroll
    for (int nb = 0; nb < 8; nb++) {
        const int ce = c0 + nb * 8 + lc * 2;      // even column
        const float2 bb = *(const float2*)(bias + ce);
        const int h = ce >> 4, d = ce & 15;
        #pragma unroll
        for (int rr = 0; rr < 2; rr++) {
            const int row = r0 + lq + rr * 8;
            const int b = row >> 11, n = row & 2047;
            __half* base = outp + ((size_t)((b * 8 + h) * 2048 + n)) * 32;
            const float x0 = (D[nb][2*rr + 0] + bb.x) * alpha;
            const float x1 = (D[nb][2*rr + 1] + bb.y) * alpha;
            const uint32_t hi2 = cvt_h2(x0, x1);
            const float2 hf = h2_to_f2(hi2);
            const uint32_t lo2 = cvt_h2(x0 - hf.x, x1 - hf.y);
            *(uint32_t*)(base + d)      = hi2;
            *(uint32_t*)(base + 16 + d) = lo2;
        }
    }
}

// ---------------- V projection + transpose (fp16-rn) ----------------
__global__ void __launch_bounds__(128) projvt_kernel(
    const float* __restrict__ value, const float* __restrict__ Wv,
    const float* __restrict__ bv)
{
    __shared__ float Wsm[16][17];
    __shared__ float bsm[16];
    __shared__ __half thi[16][128];
    const int bh = blockIdx.x >> 4, nt = blockIdx.x & 15;
    const int b = bh >> 3, h = bh & 7;
    const int t = threadIdx.x;
    if (t < 16) bsm[t] = bv[h * 16 + t];
    for (int i = t; i < 256; i += 128)
        Wsm[i >> 4][i & 15] = Wv[(h * 16 + (i >> 4)) * 16 + (i & 15)];
    __syncthreads();
    const int n = nt * 128 + t;
    const float4* a = (const float4*)(value + ((size_t)(b * NN + n) << 4));
    const float4 a0 = a[0], a1 = a[1], a2 = a[2], a3 = a[3];
    const float av[16] = {a0.x,a0.y,a0.z,a0.w, a1.x,a1.y,a1.z,a1.w,
                          a2.x,a2.y,a2.z,a2.w, a3.x,a3.y,a3.z,a3.w};
    #pragma unroll
    for (int e = 0; e < 16; e++) {
        float acc = bsm[e];
        #pragma unroll
        for (int k = 0; k < 16; k++) acc = fmaf(av[k], Wsm[e][k], acc);
        thi[e][t] = __float2half_rn(acc);
    }
    __syncthreads();
    for (int i = t; i < 2048; i += 128) {
        const int e = i >> 7, j = i & 127;
        g_vh16[((size_t)bh * 16 + e) * NN + nt * 128 + j] = thi[e][j];
    }
}

// ---------------- fp16 mma.sync flash attention (round-8 shape) ----------------
__global__ void __launch_bounds__(128) attn_mma_kernel()
{
    __shared__ __align__(16) __half Ksm[128 * 40];   // [key][hi16|lo16|pad8]
    __shared__ __align__(16) __half Vh[16 * 136];    // [e][key]

    const int tid = threadIdx.x, lane = tid & 31, wid = tid >> 5;
    const int bh = blockIdx.x >> 4, qt = blockIdx.x & 15;
    const int qrow0 = qt * 128 + wid * 32;
    const int lq = lane >> 2;
    const int lc = lane & 3;

    uint32_t qh[2][4], ql[2][4];
    {
        const __half* qb = g_q16 + ((size_t)(bh * NN + qrow0)) * 32;
        #pragma unroll
        for (int m = 0; m < 2; m++) {
            const __half* p0 = qb + (m * 16 + lq) * 32 + lc * 2;
            qh[m][0] = *(const uint32_t*)(p0);
            qh[m][1] = *(const uint32_t*)(p0 + 256);
            qh[m][2] = *(const uint32_t*)(p0 + 8);
            qh[m][3] = *(const uint32_t*)(p0 + 264);
            ql[m][0] = *(const uint32_t*)(p0 + 16);
            ql[m][1] = *(const uint32_t*)(p0 + 272);
            ql[m][2] = *(const uint32_t*)(p0 + 24);
            ql[m][3] = *(const uint32_t*)(p0 + 280);
        }
    }

    float mr[4], lrow[4];
    float o[2][2][4];
    #pragma unroll
    for (int r = 0; r < 4; r++) { mr[r] = -1e30f; lrow[r] = 0.f; }
    #pragma unroll
    for (int m = 0; m < 2; m++)
        #pragma unroll
        for (int nb = 0; nb < 2; nb++)
            #pragma unroll
            for (int i = 0; i < 4; i++) o[m][nb][i] = 0.f;

    const uint4* kg = (const uint4*)(g_k16 + ((size_t)bh * NN) * 32);
    const __half* vhg = g_vh16 + (size_t)bh * 16 * NN;

    for (int t0 = 0; t0 < NN; t0 += 128) {
        __syncthreads();
        #pragma unroll
        for (int g = 0; g < 4; g++) {
            const int j = tid + 128 * g;
            const int key = j >> 2, seg = j & 3;
            *(uint4*)(Ksm + key * 40 + seg * 8) = kg[(size_t)t0 * 4 + j];
        }
        #pragma unroll
        for (int g = 0; g < 2; g++) {
            const int j = tid + 128 * g;
            const int e = j >> 4, seg = j & 15;
            *(uint4*)(Vh + e * 136 + seg * 8) = *(const uint4*)(vhg + (size_t)e * NN + t0 + seg * 8);
        }
        __syncthreads();

        // ---- QK ----
        float S[2][16][4];
        #pragma unroll
        for (int m = 0; m < 2; m++)
            #pragma unroll
            for (int n = 0; n < 16; n++)
                #pragma unroll
                for (int i = 0; i < 4; i++) S[m][n][i] = 0.f;

        #pragma unroll
        for (int n = 0; n < 16; n++) {
            const __half* kb = Ksm + (n * 8 + lq) * 40 + lc * 2;
            const uint32_t bh0 = *(const uint32_t*)kb;
            const uint32_t bh1 = *(const uint32_t*)(kb + 8);
            const uint32_t bl0 = *(const uint32_t*)(kb + 16);
            const uint32_t bl1 = *(const uint32_t*)(kb + 24);
            #pragma unroll
            for (int m = 0; m < 2; m++) {
                mma_f16(S[m][n], qh[m], bh0, bh1);
                mma_f16(S[m][n], ql[m], bh0, bh1);
                mma_f16(S[m][n], qh[m], bl0, bl1);
            }
        }

        // ---- softmax ----
        float cm[4] = {-1e30f, -1e30f, -1e30f, -1e30f};
        #pragma unroll
        for (int m = 0; m < 2; m++)
            #pragma unroll
            for (int n = 0; n < 16; n++) {
                cm[2*m]   = fmaxf(cm[2*m],   fmaxf(S[m][n][0], S[m][n][1]));
                cm[2*m+1] = fmaxf(cm[2*m+1], fmaxf(S[m][n][2], S[m][n][3]));
            }
        #pragma unroll
        for (int r = 0; r < 4; r++) {
            const float mn = fmaxf(mr[r], qmax(cm[r]));
            const float corr = ex2f_fast(mr[r] - mn);
            mr[r] = mn; lrow[r] *= corr;
            const int m = r >> 1, h2 = (r & 1) * 2;
            #pragma unroll
            for (int nb = 0; nb < 2; nb++) {
                o[m][nb][h2]   *= corr;
                o[m][nb][h2+1] *= corr;
            }
        }
        float rs[4] = {0.f, 0.f, 0.f, 0.f};
        #pragma unroll
        for (int m = 0; m < 2; m++)
            #pragma unroll
            for (int n = 0; n < 16; n++) {
                const float p0 = ex2f_fast(S[m][n][0] - mr[2*m]);
                const float p1 = ex2f_fast(S[m][n][1] - mr[2*m]);
                const float p2 = ex2f_fast(S[m][n][2] - mr[2*m+1]);
                const float p3 = ex2f_fast(S[m][n][3] - mr[2*m+1]);
                rs[2*m]   += p0 + p1;
                rs[2*m+1] += p2 + p3;
                S[m][n][0] = __uint_as_float(cvt_h2(p0, p1));
                S[m][n][1] = __uint_as_float(cvt_h2(p2, p3));
            }
        #pragma unroll
        for (int r = 0; r < 4; r++) lrow[r] += qsum(rs[r]);

        // ---- PV ----
        #pragma unroll
        for (int kb = 0; kb < 8; kb++) {
            #pragma unroll
            for (int nb = 0; nb < 2; nb++) {
                const __half* vb = Vh + (nb * 8 + lq) * 136 + kb * 16 + lc * 2;
                const uint32_t b0 = *(const uint32_t*)vb;
                const uint32_t b1 = *(const uint32_t*)(vb + 8);
                #pragma unroll
                for (int m = 0; m < 2; m++) {
                    const uint32_t ah4[4] = {
                        __float_as_uint(S[m][2*kb][0]),   __float_as_uint(S[m][2*kb][1]),
                        __float_as_uint(S[m][2*kb+1][0]), __float_as_uint(S[m][2*kb+1][1])
                    };
                    mma_f16(o[m][nb], ah4, b0, b1);
                }
            }
        }
    }

    // ---- epilogue: fp16 ctx ----
    float inv[4];
    #pragma unroll
    for (int r = 0; r < 4; r++) inv[r] = 1.0f / lrow[r];
    const int b = bh >> 3, hh = bh & 7;
    #pragma unroll
    for (int m = 0; m < 2; m++) {
        const int rA = qrow0 + m * 16 + lq;
        #pragma unroll
        for (int nb = 0; nb < 2; nb++) {
            const int e0 = nb * 8 + lc * 2;
            __half* pA = g_ctx16 + ((size_t)(b * NN + rA)) * 128 + hh * 16 + e0;
            __half* pB = pA + 8 * 128;
            *(uint32_t*)pA = cvt_h2(o[m][nb][0] * inv[2*m],   o[m][nb][1] * inv[2*m]);
            *(uint32_t*)pB = cvt_h2(o[m][nb][2] * inv[2*m+1], o[m][nb][3] * inv[2*m+1]);
        }
    }
}

// ---------------- output projection (fp16 ctx in) ----------------
__global__ void __launch_bounds__(256) outproj_kernel(
    const float* __restrict__ Wo, const float* __restrict__ bo,
    float* __restrict__ out)
{
    __shared__ float Cs[32][128];
    __shared__ float Ws[16][132];
    const int r0 = blockIdx.x * 32;
    const uint32_t* cg16 = (const uint32_t*)(g_ctx16 + ((size_t)r0 << 7));
    float2* csv = (float2*)&Cs[0][0];
    #pragma unroll
    for (int i = 0; i < 8; i++) {
        const int idx = threadIdx.x + 256 * i;
        csv[idx] = h2_to_f2(cg16[idx]);
    }
    for (int i = threadIdx.x; i < 2048; i += 256) Ws[i >> 7][i & 127] = Wo[i];
    __syncthreads();
    const int r = threadIdx.x >> 4, c = threadIdx.x & 15;
    float acc0 = bo[c], acc1 = bo[c];
    #pragma unroll
    for (int kk = 0; kk < 128; kk += 4) {
        float4 w = *(const float4*)&Ws[c][kk];
        float4 a0 = *(const float4*)&Cs[r][kk];
        float4 a1 = *(const float4*)&Cs[r + 16][kk];
        acc0 = dot4acc(a0, w, acc0);
        acc1 = dot4acc(a1, w, acc1);
    }
    out[((size_t)(r0 + r) << 4) + c]      = acc0;
    out[((size_t)(r0 + r + 16) << 4) + c] = acc1;
}

// ---------------- launcher ----------------
extern "C" void kernel_launch(void* const* d_in, const int* in_sizes, int n_in,
                              void* d_out, int out_size)
{
    const float* query = (const float*)d_in[0];
    const float* key   = (const float*)d_in[1];
    const float* value = (const float*)d_in[2];
    const float* Wq    = (const float*)d_in[3];
    const float* bq    = (const float*)d_in[4];
    const float* Wk    = (const float*)d_in[5];
    const float* bk    = (const float*)d_in[6];
    const float* Wv    = (const float*)d_in[7];
    const float* bv    = (const float*)d_in[8];
    const float* Wo    = (const float*)d_in[9];
    const float* bo    = (const float*)d_in[10];
    float* out = (float*)d_out;

    const float alpha_q = 0.25f * 1.4426950408889634f;

    prepw_kernel<<<128, 256>>>(Wq, Wk);
    projvt_kernel<<<BHN * 16, 128>>>(value, Wv, bv);
    projqk_mma_kernel<<<dim3(128, 2), 256>>>(query, key, bq, bk, alpha_q);
    attn_mma_kernel<<<BHN * 16, 128>>>();
    outproj_kernel<<<MROWS / 32, 256>>>(Wo, bo, out);
}

// round 11
// speedup vs baseline: 1.1326x; 1.0506x over previous
#include <cuda_runtime.h>
#include <cuda_fp16.h>
#include <cstdint>

#define BB 4
#define HH 8
#define NN 2048
#define BHN (BB*HH)
#define MROWS (BB*NN)

// ---------------- scratch (static device, no allocs) ----------------
__device__ __half g_q16[BHN * NN * 32];   // [bh][n][qhi16|qlo16], 0.25*log2e folded
__device__ __half g_k16[BHN * NN * 32];   // [bh][n][khi16|klo16]
__device__ __half g_vh16[BHN * 16 * NN];  // [bh][e][n]  V^T (fp16-rn)
__device__ __half g_ctx16[MROWS * 128];   // [b*N+n][h*16+e]  fp16
__device__ __half g_Wh[2 * 128 * 128];    // W hi: [q|k][c][k]
__device__ __half g_Wl[2 * 128 * 128];    // W lo residual

// ---------------- helpers ----------------
__device__ __forceinline__ float ex2f_fast(float x) {
    float y; asm("ex2.approx.ftz.f32 %0, %1;" : "=f"(y) : "f"(x)); return y;
}
__device__ __forceinline__ float dot4acc(float4 a, float4 b, float t) {
    t = fmaf(a.x, b.x, t); t = fmaf(a.y, b.y, t);
    t = fmaf(a.z, b.z, t); t = fmaf(a.w, b.w, t);
    return t;
}
__device__ __forceinline__ float qmax(float v) {
    v = fmaxf(v, __shfl_xor_sync(0xFFFFFFFFu, v, 1));
    v = fmaxf(v, __shfl_xor_sync(0xFFFFFFFFu, v, 2));
    return v;
}
__device__ __forceinline__ float qsum(float v) {
    v += __shfl_xor_sync(0xFFFFFFFFu, v, 1);
    v += __shfl_xor_sync(0xFFFFFFFFu, v, 2);
    return v;
}
__device__ __forceinline__ void mma_f16(float* d, const uint32_t* a,
                                        uint32_t b0, uint32_t b1) {
    asm volatile(
        "mma.sync.aligned.m16n8k16.row.col.f32.f16.f16.f32 "
        "{%0,%1,%2,%3}, {%4,%5,%6,%7}, {%8,%9}, {%0,%1,%2,%3};"
        : "+f"(d[0]), "+f"(d[1]), "+f"(d[2]), "+f"(d[3])
        : "r"(a[0]), "r"(a[1]), "r"(a[2]), "r"(a[3]), "r"(b0), "r"(b1));
}
// packs: low half <- lo, high half <- hi
__device__ __forceinline__ uint32_t cvt_h2(float lo, float hi) {
    uint32_t r;
    asm("cvt.rn.f16x2.f32 %0, %1, %2;" : "=r"(r) : "f"(hi), "f"(lo));
    return r;
}
__device__ __forceinline__ float2 h2_to_f2(uint32_t u) {
    return __half22float2(*reinterpret_cast<__half2*>(&u));
}

// ---------------- V projection + transpose (fp16) + W hi/lo prep (fused) ----------------
// blocks [0,512): projvt; blocks [512,768): Wq/Wk split.
__global__ void __launch_bounds__(128) projvt_prepw_kernel(
    const float* __restrict__ value, const float* __restrict__ Wv,
    const float* __restrict__ bv,
    const float* __restrict__ Wq, const float* __restrict__ Wk)
{
    if (blockIdx.x >= 512) {
        const int idx = (blockIdx.x - 512) * 128 + threadIdx.x;  // 0..32767
        const int m = idx >> 14, rest = idx & 16383;
        const float x = (m ? Wk : Wq)[rest];
        const __half hi = __float2half_rn(x);
        g_Wh[idx] = hi;
        g_Wl[idx] = __float2half_rn(x - __half2float(hi));
        return;
    }
    __shared__ float Wsm[16][17];
    __shared__ float bsm[16];
    __shared__ __half thi[16][128];
    const int bh = blockIdx.x >> 4, nt = blockIdx.x & 15;
    const int b = bh >> 3, h = bh & 7;
    const int t = threadIdx.x;
    if (t < 16) bsm[t] = bv[h * 16 + t];
    for (int i = t; i < 256; i += 128)
        Wsm[i >> 4][i & 15] = Wv[(h * 16 + (i >> 4)) * 16 + (i & 15)];
    __syncthreads();
    const int n = nt * 128 + t;
    const float4* a = (const float4*)(value + ((size_t)(b * NN + n) << 4));
    const float4 a0 = a[0], a1 = a[1], a2 = a[2], a3 = a[3];
    const float av[16] = {a0.x,a0.y,a0.z,a0.w, a1.x,a1.y,a1.z,a1.w,
                          a2.x,a2.y,a2.z,a2.w, a3.x,a3.y,a3.z,a3.w};
    #pragma unroll
    for (int e = 0; e < 16; e++) {
        float acc = bsm[e];
        #pragma unroll
        for (int k = 0; k < 16; k++) acc = fmaf(av[k], Wsm[e][k], acc);
        thi[e][t] = __float2half_rn(acc);
    }
    __syncthreads();
    for (int i = t; i < 2048; i += 128) {
        const int e = i >> 7, j = i & 127;
        g_vh16[((size_t)bh * 16 + e) * NN + nt * 128 + j] = thi[e][j];
    }
}

// ---------------- Q/K projection on tensor cores ----------------
__global__ void __launch_bounds__(256) projqk_mma_kernel(
    const float* __restrict__ Aq, const float* __restrict__ Ak,
    const float* __restrict__ bq, const float* __restrict__ bk, float alpha_q)
{
    const bool is_k = (blockIdx.y != 0);
    const float* A    = is_k ? Ak : Aq;
    const float* bias = is_k ? bk : bq;
    const __half* Wh  = g_Wh + (is_k ? 16384 : 0);
    const __half* Wl  = g_Wl + (is_k ? 16384 : 0);
    __half* outp      = is_k ? g_k16 : g_q16;
    const float alpha = is_k ? 1.0f : alpha_q;

    const int tid = threadIdx.x, lane = tid & 31, wid = tid >> 5;
    const int rg = wid >> 1, cg = wid & 1;
    const int lq = lane >> 2, lc = lane & 3;
    const int r0 = blockIdx.x * 64 + rg * 16;
    const int c0 = cg * 64;

    uint32_t ah[8][4], al[8][4];
    {
        const float* Ar0 = A + (size_t)(r0 + lq) * 128;
        const float* Ar1 = Ar0 + 8 * 128;
        #pragma unroll
        for (int ks = 0; ks < 8; ks++) {
            const int k0 = ks * 16 + lc * 2;
            float2 f0 = *(const float2*)(Ar0 + k0);
            float2 f1 = *(const float2*)(Ar1 + k0);
            float2 f2 = *(const float2*)(Ar0 + k0 + 8);
            float2 f3 = *(const float2*)(Ar1 + k0 + 8);
            ah[ks][0] = cvt_h2(f0.x, f0.y);
            ah[ks][1] = cvt_h2(f1.x, f1.y);
            ah[ks][2] = cvt_h2(f2.x, f2.y);
            ah[ks][3] = cvt_h2(f3.x, f3.y);
            float2 h0 = h2_to_f2(ah[ks][0]), h1 = h2_to_f2(ah[ks][1]);
            float2 h2 = h2_to_f2(ah[ks][2]), h3 = h2_to_f2(ah[ks][3]);
            al[ks][0] = cvt_h2(f0.x - h0.x, f0.y - h0.y);
            al[ks][1] = cvt_h2(f1.x - h1.x, f1.y - h1.y);
            al[ks][2] = cvt_h2(f2.x - h2.x, f2.y - h2.y);
            al[ks][3] = cvt_h2(f3.x - h3.x, f3.y - h3.y);
        }
    }

    float D[8][4];
    #pragma unroll
    for (int nb = 0; nb < 8; nb++)
        #pragma unroll
        for (int i = 0; i < 4; i++) D[nb][i] = 0.f;

    #pragma unroll
    for (int nb = 0; nb < 8; nb++) {
        const int c = c0 + nb * 8 + lq;
        const __half* whp = Wh + (size_t)c * 128;
        const __half* wlp = Wl + (size_t)c * 128;
        #pragma unroll
        for (int ks = 0; ks < 8; ks++) {
            const int k0 = ks * 16 + lc * 2;
            const uint32_t bh0 = *(const uint32_t*)(whp + k0);
            const uint32_t bh1 = *(const uint32_t*)(whp + k0 + 8);
            const uint32_t bl0 = *(const uint32_t*)(wlp + k0);
            const uint32_t bl1 = *(const uint32_t*)(wlp + k0 + 8);
            mma_f16(D[nb], ah[ks], bh0, bh1);
            mma_f16(D[nb], al[ks], bh0, bh1);
            mma_f16(D[nb], ah[ks], bl0, bl1);
        }
    }

    #pragma unroll
    for (int nb = 0; nb < 8; nb++) {
        const int ce = c0 + nb * 8 + lc * 2;
        const float2 bb = *(const float2*)(bias + ce);
        const int h = ce >> 4, d = ce & 15;
        #pragma unroll
        for (int rr = 0; rr < 2; rr++) {
            const int row = r0 + lq + rr * 8;
            const int b = row >> 11, n = row & 2047;
            __half* base = outp + ((size_t)((b * 8 + h) * 2048 + n)) * 32;
            const float x0 = (D[nb][2*rr + 0] + bb.x) * alpha;
            const float x1 = (D[nb][2*rr + 1] + bb.y) * alpha;
            const uint32_t hi2 = cvt_h2(x0, x1);
            const float2 hf = h2_to_f2(hi2);
            const uint32_t lo2 = cvt_h2(x0 - hf.x, x1 - hf.y);
            *(uint32_t*)(base + d)      = hi2;
            *(uint32_t*)(base + 16 + d) = lo2;
        }
    }
}

// ---------------- fp16 mma.sync flash attention ----------------
// 1024 CTAs = 32 bh x 32 q-tiles of 64 rows; 4 warps; warp owns 16 q-rows.
// Forced 4 CTAs/SM (16 warps/SM) to overlap softmax of one CTA with MMAs of another.
__global__ void __launch_bounds__(128, 4) attn_mma_kernel()
{
    __shared__ __align__(16) __half Ksm[128 * 40];   // [key][hi16|lo16|pad8]
    __shared__ __align__(16) __half Vh[16 * 136];    // [e][key]

    const int tid = threadIdx.x, lane = tid & 31, wid = tid >> 5;
    const int bh = blockIdx.x >> 5, qt = blockIdx.x & 31;
    const int qrow0 = qt * 64 + wid * 16;
    const int lq = lane >> 2;
    const int lc = lane & 3;

    // Q fragments hi/lo (warp = one m16 block)
    uint32_t qh[4], ql[4];
    {
        const __half* p0 = g_q16 + ((size_t)(bh * NN + qrow0 + lq)) * 32 + lc * 2;
        qh[0] = *(const uint32_t*)(p0);
        qh[1] = *(const uint32_t*)(p0 + 256);
        qh[2] = *(const uint32_t*)(p0 + 8);
        qh[3] = *(const uint32_t*)(p0 + 264);
        ql[0] = *(const uint32_t*)(p0 + 16);
        ql[1] = *(const uint32_t*)(p0 + 272);
        ql[2] = *(const uint32_t*)(p0 + 24);
        ql[3] = *(const uint32_t*)(p0 + 280);
    }

    float mr[2] = {-1e30f, -1e30f}, lrow[2] = {0.f, 0.f};
    float o[2][4];
    #pragma unroll
    for (int nb = 0; nb < 2; nb++)
        #pragma unroll
        for (int i = 0; i < 4; i++) o[nb][i] = 0.f;

    const uint4* kg = (const uint4*)(g_k16 + ((size_t)bh * NN) * 32);
    const __half* vhg = g_vh16 + (size_t)bh * 16 * NN;

    for (int t0 = 0; t0 < NN; t0 += 128) {
        __syncthreads();
        #pragma unroll
        for (int g = 0; g < 4; g++) {
            const int j = tid + 128 * g;
            const int key = j >> 2, seg = j & 3;
            *(uint4*)(Ksm + key * 40 + seg * 8) = kg[(size_t)t0 * 4 + j];
        }
        #pragma unroll
        for (int g = 0; g < 2; g++) {
            const int j = tid + 128 * g;
            const int e = j >> 4, seg = j & 15;
            *(uint4*)(Vh + e * 136 + seg * 8) = *(const uint4*)(vhg + (size_t)e * NN + t0 + seg * 8);
        }
        __syncthreads();

        // ---- QK: 3 compensated MMAs per n-block ----
        float S[16][4];
        #pragma unroll
        for (int n = 0; n < 16; n++)
            #pragma unroll
            for (int i = 0; i < 4; i++) S[n][i] = 0.f;

        #pragma unroll
        for (int n = 0; n < 16; n++) {
            const __half* kb = Ksm + (n * 8 + lq) * 40 + lc * 2;
            const uint32_t bh0 = *(const uint32_t*)kb;
            const uint32_t bh1 = *(const uint32_t*)(kb + 8);
            const uint32_t bl0 = *(const uint32_t*)(kb + 16);
            const uint32_t bl1 = *(const uint32_t*)(kb + 24);
            mma_f16(S[n], qh, bh0, bh1);
            mma_f16(S[n], ql, bh0, bh1);
            mma_f16(S[n], qh, bl0, bl1);
        }

        // ---- softmax (rows lq, lq+8) ----
        float cm0 = -1e30f, cm1 = -1e30f;
        #pragma unroll
        for (int n = 0; n < 16; n++) {
            cm0 = fmaxf(cm0, fmaxf(S[n][0], S[n][1]));
            cm1 = fmaxf(cm1, fmaxf(S[n][2], S[n][3]));
        }
        {
            const float mn0 = fmaxf(mr[0], qmax(cm0));
            const float c0 = ex2f_fast(mr[0] - mn0);
            mr[0] = mn0; lrow[0] *= c0;
            const float mn1 = fmaxf(mr[1], qmax(cm1));
            const float c1 = ex2f_fast(mr[1] - mn1);
            mr[1] = mn1; lrow[1] *= c1;
            #pragma unroll
            for (int nb = 0; nb < 2; nb++) {
                o[nb][0] *= c0; o[nb][1] *= c0;
                o[nb][2] *= c1; o[nb][3] *= c1;
            }
        }
        float rs0 = 0.f, rs1 = 0.f;
        #pragma unroll
        for (int n = 0; n < 16; n++) {
            const float p0 = ex2f_fast(S[n][0] - mr[0]);
            const float p1 = ex2f_fast(S[n][1] - mr[0]);
            const float p2 = ex2f_fast(S[n][2] - mr[1]);
            const float p3 = ex2f_fast(S[n][3] - mr[1]);
            rs0 += p0 + p1;
            rs1 += p2 + p3;
            S[n][0] = __uint_as_float(cvt_h2(p0, p1));
            S[n][1] = __uint_as_float(cvt_h2(p2, p3));
        }
        lrow[0] += qsum(rs0);
        lrow[1] += qsum(rs1);

        // ---- PV ----
        #pragma unroll
        for (int kb = 0; kb < 8; kb++) {
            const uint32_t ah4[4] = {
                __float_as_uint(S[2*kb][0]),   __float_as_uint(S[2*kb][1]),
                __float_as_uint(S[2*kb+1][0]), __float_as_uint(S[2*kb+1][1])
            };
            #pragma unroll
            for (int nb = 0; nb < 2; nb++) {
                const __half* vb = Vh + (nb * 8 + lq) * 136 + kb * 16 + lc * 2;
                const uint32_t b0 = *(const uint32_t*)vb;
                const uint32_t b1 = *(const uint32_t*)(vb + 8);
                mma_f16(o[nb], ah4, b0, b1);
            }
        }
    }

    // ---- epilogue: fp16 ctx ----
    const float inv0 = 1.0f / lrow[0];
    const float inv1 = 1.0f / lrow[1];
    const int b = bh >> 3, hh = bh & 7;
    const int rA = qrow0 + lq;
    #pragma unroll
    for (int nb = 0; nb < 2; nb++) {
        const int e0 = nb * 8 + lc * 2;
        __half* pA = g_ctx16 + ((size_t)(b * NN + rA)) * 128 + hh * 16 + e0;
        __half* pB = pA + 8 * 128;
        *(uint32_t*)pA = cvt_h2(o[nb][0] * inv0, o[nb][1] * inv0);
        *(uint32_t*)pB = cvt_h2(o[nb][2] * inv1, o[nb][3] * inv1);
    }
}

// ---------------- output projection (fp16 ctx in) ----------------
__global__ void __launch_bounds__(256) outproj_kernel(
    const float* __restrict__ Wo, const float* __restrict__ bo,
    float* __restrict__ out)
{
    __shared__ float Cs[32][128];
    __shared__ float Ws[16][132];
    const int r0 = blockIdx.x * 32;
    const uint32_t* cg16 = (const uint32_t*)(g_ctx16 + ((size_t)r0 << 7));
    float2* csv = (float2*)&Cs[0][0];
    #pragma unroll
    for (int i = 0; i < 8; i++) {
        const int idx = threadIdx.x + 256 * i;
        csv[idx] = h2_to_f2(cg16[idx]);
    }
    for (int i = threadIdx.x; i < 2048; i += 256) Ws[i >> 7][i & 127] = Wo[i];
    __syncthreads();
    const int r = threadIdx.x >> 4, c = threadIdx.x & 15;
    float acc0 = bo[c], acc1 = bo[c];
    #pragma unroll
    for (int kk = 0; kk < 128; kk += 4) {
        float4 w = *(const float4*)&Ws[c][kk];
        float4 a0 = *(const float4*)&Cs[r][kk];
        float4 a1 = *(const float4*)&Cs[r + 16][kk];
        acc0 = dot4acc(a0, w, acc0);
        acc1 = dot4acc(a1, w, acc1);
    }
    out[((size_t)(r0 + r) << 4) + c]      = acc0;
    out[((size_t)(r0 + r + 16) << 4) + c] = acc1;
}

// ---------------- launcher ----------------
extern "C" void kernel_launch(void* const* d_in, const int* in_sizes, int n_in,
                              void* d_out, int out_size)
{
    const float* query = (const float*)d_in[0];
    const float* key   = (const float*)d_in[1];
    const float* value = (const float*)d_in[2];
    const float* Wq    = (const float*)d_in[3];
    const float* bq    = (const float*)d_in[4];
    const float* Wk    = (const float*)d_in[5];
    const float* bk    = (const float*)d_in[6];
    const float* Wv    = (const float*)d_in[7];
    const float* bv    = (const float*)d_in[8];
    const float* Wo    = (const float*)d_in[9];
    const float* bo    = (const float*)d_in[10];
    float* out = (float*)d_out;

    const float alpha_q = 0.25f * 1.4426950408889634f;

    projvt_prepw_kernel<<<768, 128>>>(value, Wv, bv, Wq, Wk);
    projqk_mma_kernel<<<dim3(128, 2), 256>>>(query, key, bq, bk, alpha_q);
    attn_mma_kernel<<<BHN * 32, 128>>>();
    outproj_kernel<<<MROWS / 32, 256>>>(Wo, bo, out);
}